// round 1
// baseline (speedup 1.0000x reference)
#include <cuda_runtime.h>
#include <math.h>

#define S_LEN  2048
#define BATCH  2
#define DMODEL 4096
#define NH     32
#define NKV    8
#define HDIM   128
#define MROWS  (BATCH * S_LEN)   // 4096

// Scratch (allocation-free rule: __device__ globals)
__device__ __align__(16) float g_q[(size_t)MROWS * NH * HDIM];   // 64 MB
__device__ __align__(16) float g_k[(size_t)MROWS * NKV * HDIM];  // 16 MB
__device__ __align__(16) float g_v[(size_t)MROWS * NKV * HDIM];  // 16 MB
__device__ __align__(16) float g_o[(size_t)MROWS * NH * HDIM];   // 64 MB

// ---------------------------------------------------------------------------
// SGEMM: C[M,N] = A[M,K] @ B[K,N], all row-major contiguous.
// 128x128 block tile, BK=8, 256 threads, 8x8 per thread (4+64 split).
// Requires M,N % 128 == 0, K % 8 == 0 (true for all calls here).
// ---------------------------------------------------------------------------
__global__ __launch_bounds__(256) void sgemm128(
    const float* __restrict__ A, const float* __restrict__ B,
    float* __restrict__ C, int M, int N, int K)
{
    __shared__ float As[8][128];   // transposed A tile: As[k][m]
    __shared__ float Bs[8][128];

    const int tid  = threadIdx.x;
    const int row0 = blockIdx.y * 128;
    const int col0 = blockIdx.x * 128;

    const int aRow = tid >> 1;            // 0..127
    const int aCol = (tid & 1) << 2;      // 0 or 4
    const int bRow = tid >> 5;            // 0..7
    const int bCol = (tid & 31) << 2;     // 0..124

    const int tx = tid & 15;
    const int ty = tid >> 4;

    float acc[8][8];
#pragma unroll
    for (int i = 0; i < 8; i++)
#pragma unroll
        for (int j = 0; j < 8; j++) acc[i][j] = 0.0f;

    const float* Ap = A + (size_t)(row0 + aRow) * K + aCol;
    const float* Bp = B + (size_t)bRow * N + col0 + bCol;

    for (int k0 = 0; k0 < K; k0 += 8) {
        float4 av = *(const float4*)(Ap + k0);
        float4 bv = *(const float4*)(Bp + (size_t)k0 * N);
        As[aCol + 0][aRow] = av.x;
        As[aCol + 1][aRow] = av.y;
        As[aCol + 2][aRow] = av.z;
        As[aCol + 3][aRow] = av.w;
        *(float4*)&Bs[bRow][bCol] = bv;
        __syncthreads();

#pragma unroll
        for (int kk = 0; kk < 8; kk++) {
            float4 a0 = *(const float4*)&As[kk][ty * 4];
            float4 a1 = *(const float4*)&As[kk][ty * 4 + 64];
            float4 b0 = *(const float4*)&Bs[kk][tx * 4];
            float4 b1 = *(const float4*)&Bs[kk][tx * 4 + 64];
            float ra[8] = {a0.x, a0.y, a0.z, a0.w, a1.x, a1.y, a1.z, a1.w};
            float rb[8] = {b0.x, b0.y, b0.z, b0.w, b1.x, b1.y, b1.z, b1.w};
#pragma unroll
            for (int i = 0; i < 8; i++)
#pragma unroll
                for (int j = 0; j < 8; j++)
                    acc[i][j] = fmaf(ra[i], rb[j], acc[i][j]);
        }
        __syncthreads();
    }

#pragma unroll
    for (int i = 0; i < 8; i++) {
        int r = row0 + ((i < 4) ? (ty * 4 + i) : (64 + ty * 4 + (i - 4)));
        float4 v0 = make_float4(acc[i][0], acc[i][1], acc[i][2], acc[i][3]);
        float4 v1 = make_float4(acc[i][4], acc[i][5], acc[i][6], acc[i][7]);
        *(float4*)&C[(size_t)r * N + col0 + tx * 4]      = v0;
        *(float4*)&C[(size_t)r * N + col0 + tx * 4 + 64] = v1;
    }
}

// ---------------------------------------------------------------------------
// RoPE (interleaved pairs): x[...,2p],x[...,2p+1] rotated by (cos,sin)[s,p].
// idx enumerates (b*S+s, head, p) with 64 pairs per head.
// ---------------------------------------------------------------------------
__global__ void rope_kernel(float* __restrict__ q, const float* __restrict__ cs,
                            const float* __restrict__ sn, int nheads, int total)
{
    int idx = blockIdx.x * blockDim.x + threadIdx.x;
    if (idx >= total) return;
    int p    = idx & 63;
    int rest = idx >> 6;               // (b*S+s)*nheads + h
    int bs   = rest / nheads;          // b*S + s
    int s    = bs & (S_LEN - 1);
    float c  = cs[s * 64 + p];
    float sv = sn[s * 64 + p];
    size_t off = (size_t)rest * HDIM + 2 * p;
    float x0 = q[off], x1 = q[off + 1];
    q[off]     = x0 * c  - x1 * sv;
    q[off + 1] = x0 * sv + x1 * c;
}

// ---------------------------------------------------------------------------
// Causal flash attention, fp32. Grid: (S/BR, NH, BATCH), 256 threads.
// BR=BC=64, HD=128. Per-thread: 4 q-rows (ty*4+i) x 8 out-cols (tx*4, tx*4+64).
// ---------------------------------------------------------------------------
#define BR 64
#define BC 64
#define LDQ 132
#define LDK 129
#define LDV 132
#define LDP 65
#define FLASH_SMEM ((BR * LDQ + BC * LDK + BC * LDV + BR * LDP) * 4)

__global__ __launch_bounds__(256) void flash_kernel(
    const float* __restrict__ Q, const float* __restrict__ Kg,
    const float* __restrict__ Vg, float* __restrict__ O)
{
    extern __shared__ float sm[];
    float* Qs = sm;
    float* Ks = Qs + BR * LDQ;
    float* Vs = Ks + BC * LDK;
    float* Ps = Vs + BC * LDV;

    const int tid = threadIdx.x;
    const int tx  = tid & 15;
    const int ty  = tid >> 4;
    const int qt  = blockIdx.x;
    const int h   = blockIdx.y;
    const int b   = blockIdx.z;
    const int g   = h >> 2;            // NREP = 4
    const int q0  = qt * BR;

    // Load Q tile (coalesced on d)
    for (int idx = tid; idx < BR * HDIM; idx += 256) {
        int r = idx >> 7, d = idx & 127;
        Qs[r * LDQ + d] = Q[((size_t)(b * S_LEN + q0 + r) * NH + h) * HDIM + d];
    }

    float m_prev[4], l[4], acc[4][8];
#pragma unroll
    for (int i = 0; i < 4; i++) {
        m_prev[i] = -3.0e38f;
        l[i] = 0.0f;
#pragma unroll
        for (int c = 0; c < 8; c++) acc[i][c] = 0.0f;
    }

    const float scale = 0.08838834764831845f;   // 1/sqrt(128)

    for (int jt = 0; jt <= qt; jt++) {
        const int j0 = jt * BC;
        __syncthreads();   // protect K/V/P from previous iteration readers

        for (int idx = tid; idx < BC * HDIM; idx += 256) {
            int r = idx >> 7, d = idx & 127;
            Ks[r * LDK + d] = Kg[((size_t)(b * S_LEN + j0 + r) * NKV + g) * HDIM + d];
        }
        for (int idx = tid; idx < BC * (HDIM / 4); idx += 256) {
            int r = idx >> 5, c4 = idx & 31;
            float4 vv = *(const float4*)&Vg[((size_t)(b * S_LEN + j0 + r) * NKV + g) * HDIM + c4 * 4];
            *(float4*)&Vs[r * LDV + c4 * 4] = vv;
        }
        __syncthreads();

        // S = Q K^T (4x4 per thread)
        float sv[4][4];
#pragma unroll
        for (int i = 0; i < 4; i++)
#pragma unroll
            for (int j = 0; j < 4; j++) sv[i][j] = 0.0f;

#pragma unroll 4
        for (int d = 0; d < HDIM; d++) {
            float aq[4], bk[4];
#pragma unroll
            for (int i = 0; i < 4; i++) aq[i] = Qs[(ty * 4 + i) * LDQ + d];
#pragma unroll
            for (int j = 0; j < 4; j++) bk[j] = Ks[(tx * 4 + j) * LDK + d];
#pragma unroll
            for (int i = 0; i < 4; i++)
#pragma unroll
                for (int j = 0; j < 4; j++)
                    sv[i][j] = fmaf(aq[i], bk[j], sv[i][j]);
        }

        const bool diag = (jt == qt);
#pragma unroll
        for (int i = 0; i < 4; i++) {
            int qi = q0 + ty * 4 + i;
#pragma unroll
            for (int j = 0; j < 4; j++) {
                float s = sv[i][j] * scale;
                if (diag && (j0 + tx * 4 + j > qi)) s = -1.0e30f;
                sv[i][j] = s;
            }
        }

        // Online softmax (reduce over 16 tx lanes; xor<16 stays in-group)
#pragma unroll
        for (int i = 0; i < 4; i++) {
            float mt = fmaxf(fmaxf(sv[i][0], sv[i][1]), fmaxf(sv[i][2], sv[i][3]));
#pragma unroll
            for (int off = 8; off > 0; off >>= 1)
                mt = fmaxf(mt, __shfl_xor_sync(0xffffffffu, mt, off));
            float mnew = fmaxf(m_prev[i], mt);
            float corr = __expf(m_prev[i] - mnew);
            float rl = 0.0f;
#pragma unroll
            for (int j = 0; j < 4; j++) {
                float p = __expf(sv[i][j] - mnew);
                Ps[(ty * 4 + i) * LDP + tx * 4 + j] = p;
                rl += p;
            }
#pragma unroll
            for (int off = 8; off > 0; off >>= 1)
                rl += __shfl_xor_sync(0xffffffffu, rl, off);
            l[i] = l[i] * corr + rl;
            m_prev[i] = mnew;
#pragma unroll
            for (int c = 0; c < 8; c++) acc[i][c] *= corr;
        }
        __syncthreads();

        // O += P @ V
#pragma unroll 2
        for (int j = 0; j < BC; j++) {
            float4 v0 = *(const float4*)&Vs[j * LDV + tx * 4];
            float4 v1 = *(const float4*)&Vs[j * LDV + 64 + tx * 4];
#pragma unroll
            for (int i = 0; i < 4; i++) {
                float p = Ps[(ty * 4 + i) * LDP + j];
                acc[i][0] = fmaf(p, v0.x, acc[i][0]);
                acc[i][1] = fmaf(p, v0.y, acc[i][1]);
                acc[i][2] = fmaf(p, v0.z, acc[i][2]);
                acc[i][3] = fmaf(p, v0.w, acc[i][3]);
                acc[i][4] = fmaf(p, v1.x, acc[i][4]);
                acc[i][5] = fmaf(p, v1.y, acc[i][5]);
                acc[i][6] = fmaf(p, v1.z, acc[i][6]);
                acc[i][7] = fmaf(p, v1.w, acc[i][7]);
            }
        }
    }

    // Epilogue: O / l
#pragma unroll
    for (int i = 0; i < 4; i++) {
        float inv = 1.0f / l[i];
        size_t base = ((size_t)(b * S_LEN + q0 + ty * 4 + i) * NH + h) * HDIM;
#pragma unroll
        for (int cc = 0; cc < 4; cc++) {
            O[base + tx * 4 + cc]      = acc[i][cc]     * inv;
            O[base + 64 + tx * 4 + cc] = acc[i][cc + 4] * inv;
        }
    }
}

// ---------------------------------------------------------------------------
// Launch: QKV GEMMs -> RoPE(q,k) -> flash attention -> output GEMM
// Inputs (metadata order): x, wq, wk, wv, wo, freqs_cos, freqs_sin, mask, start_pos
// mask/start_pos unused (causal, start_pos=0).
// ---------------------------------------------------------------------------
extern "C" void kernel_launch(void* const* d_in, const int* in_sizes, int n_in,
                              void* d_out, int out_size)
{
    const float* x  = (const float*)d_in[0];
    const float* wq = (const float*)d_in[1];
    const float* wk = (const float*)d_in[2];
    const float* wv = (const float*)d_in[3];
    const float* wo = (const float*)d_in[4];
    const float* fc = (const float*)d_in[5];
    const float* fs = (const float*)d_in[6];
    float* out = (float*)d_out;

    float *q, *k, *v, *o;
    cudaGetSymbolAddress((void**)&q, g_q);
    cudaGetSymbolAddress((void**)&k, g_k);
    cudaGetSymbolAddress((void**)&v, g_v);
    cudaGetSymbolAddress((void**)&o, g_o);

    // QKV projections
    sgemm128<<<dim3((NH * HDIM) / 128,  MROWS / 128), 256>>>(x, wq, q, MROWS, NH * HDIM,  DMODEL);
    sgemm128<<<dim3((NKV * HDIM) / 128, MROWS / 128), 256>>>(x, wk, k, MROWS, NKV * HDIM, DMODEL);
    sgemm128<<<dim3((NKV * HDIM) / 128, MROWS / 128), 256>>>(x, wv, v, MROWS, NKV * HDIM, DMODEL);

    // RoPE
    int qtot = MROWS * NH  * 64;
    int ktot = MROWS * NKV * 64;
    rope_kernel<<<(qtot + 255) / 256, 256>>>(q, fc, fs, NH,  qtot);
    rope_kernel<<<(ktot + 255) / 256, 256>>>(k, fc, fs, NKV, ktot);

    // Attention
    cudaFuncSetAttribute(flash_kernel, cudaFuncAttributeMaxDynamicSharedMemorySize, FLASH_SMEM);
    flash_kernel<<<dim3(S_LEN / BR, NH, BATCH), 256, FLASH_SMEM>>>(q, k, v, o);

    // Output projection
    sgemm128<<<dim3(DMODEL / 128, MROWS / 128), 256>>>(o, wo, out, MROWS, DMODEL, NH * HDIM);
}

// round 4
// speedup vs baseline: 1.7491x; 1.7491x over previous
#include <cuda_runtime.h>
#include <cuda_bf16.h>
#include <math.h>
#include <stdint.h>

#define S_LEN  2048
#define BATCH  2
#define DMODEL 4096
#define NH     32
#define NKV    8
#define HDIM   128
#define MROWS  (BATCH * S_LEN)   // 4096

// ---------------- scratch (__device__ globals; no allocs allowed) ----------
__device__ __align__(16) float g_q[(size_t)MROWS * NH * HDIM];
__device__ __align__(16) float g_k[(size_t)MROWS * NKV * HDIM];
__device__ __align__(16) float g_v[(size_t)MROWS * NKV * HDIM];
__device__ __align__(16) float g_o[(size_t)MROWS * NH * HDIM];

__device__ __align__(16) __nv_bfloat16 g_xh[(size_t)MROWS * DMODEL];
__device__ __align__(16) __nv_bfloat16 g_xl[(size_t)MROWS * DMODEL];
__device__ __align__(16) __nv_bfloat16 g_wqt_h[(size_t)DMODEL * DMODEL];
__device__ __align__(16) __nv_bfloat16 g_wqt_l[(size_t)DMODEL * DMODEL];
__device__ __align__(16) __nv_bfloat16 g_wkt_h[(size_t)(NKV*HDIM) * DMODEL];
__device__ __align__(16) __nv_bfloat16 g_wkt_l[(size_t)(NKV*HDIM) * DMODEL];
__device__ __align__(16) __nv_bfloat16 g_wvt_h[(size_t)(NKV*HDIM) * DMODEL];
__device__ __align__(16) __nv_bfloat16 g_wvt_l[(size_t)(NKV*HDIM) * DMODEL];
__device__ __align__(16) __nv_bfloat16 g_wot_h[(size_t)DMODEL * DMODEL];
__device__ __align__(16) __nv_bfloat16 g_wot_l[(size_t)DMODEL * DMODEL];
__device__ __align__(16) __nv_bfloat16 g_oh[(size_t)MROWS * DMODEL];
__device__ __align__(16) __nv_bfloat16 g_ol[(size_t)MROWS * DMODEL];

// ---------------- helpers ---------------------------------------------------
__device__ __forceinline__ uint32_t smem_u32(const void* p) {
    return (uint32_t)__cvta_generic_to_shared(p);
}
__device__ __forceinline__ void cp16(uint32_t dst, const void* src) {
    asm volatile("cp.async.ca.shared.global [%0], [%1], 16;" :: "r"(dst), "l"(src) : "memory");
}
__device__ __forceinline__ void cp_commit() {
    asm volatile("cp.async.commit_group;" ::: "memory");
}
__device__ __forceinline__ void ldsm4(uint32_t& r0, uint32_t& r1, uint32_t& r2, uint32_t& r3,
                                      uint32_t addr) {
    asm volatile("ldmatrix.sync.aligned.m8n8.x4.shared.b16 {%0,%1,%2,%3}, [%4];"
                 : "=r"(r0), "=r"(r1), "=r"(r2), "=r"(r3) : "r"(addr));
}
__device__ __forceinline__ void mma_bf16(float* d, const uint32_t* a, const uint32_t* b) {
    asm volatile("mma.sync.aligned.m16n8k16.row.col.f32.bf16.bf16.f32 "
                 "{%0,%1,%2,%3}, {%4,%5,%6,%7}, {%8,%9}, {%0,%1,%2,%3};"
                 : "+f"(d[0]), "+f"(d[1]), "+f"(d[2]), "+f"(d[3])
                 : "r"(a[0]), "r"(a[1]), "r"(a[2]), "r"(a[3]), "r"(b[0]), "r"(b[1]));
}

// ---------------------------------------------------------------------------
// fp32 -> (hi, lo) bf16 split, elementwise
// ---------------------------------------------------------------------------
__global__ void split4_kernel(const float* __restrict__ in,
                              __nv_bfloat16* __restrict__ h,
                              __nv_bfloat16* __restrict__ l, int n4)
{
    int i = blockIdx.x * blockDim.x + threadIdx.x;
    if (i >= n4) return;
    float4 x = ((const float4*)in)[i];
    __nv_bfloat16 h0 = __float2bfloat16(x.x), h1 = __float2bfloat16(x.y);
    __nv_bfloat16 h2 = __float2bfloat16(x.z), h3 = __float2bfloat16(x.w);
    __nv_bfloat16 l0 = __float2bfloat16(x.x - __bfloat162float(h0));
    __nv_bfloat16 l1 = __float2bfloat16(x.y - __bfloat162float(h1));
    __nv_bfloat16 l2 = __float2bfloat16(x.z - __bfloat162float(h2));
    __nv_bfloat16 l3 = __float2bfloat16(x.w - __bfloat162float(h3));
    ((__nv_bfloat162*)h)[2*i]   = __nv_bfloat162(h0, h1);
    ((__nv_bfloat162*)h)[2*i+1] = __nv_bfloat162(h2, h3);
    ((__nv_bfloat162*)l)[2*i]   = __nv_bfloat162(l0, l1);
    ((__nv_bfloat162*)l)[2*i+1] = __nv_bfloat162(l2, l3);
}

// ---------------------------------------------------------------------------
// W[K,N] fp32 -> WT[N,K] (hi, lo) bf16, tiled transpose
// ---------------------------------------------------------------------------
__global__ void split_transpose_kernel(const float* __restrict__ W,
                                       __nv_bfloat16* __restrict__ Th,
                                       __nv_bfloat16* __restrict__ Tl,
                                       int K, int N)
{
    __shared__ float t[32][33];
    int k0 = blockIdx.y * 32, n0 = blockIdx.x * 32;
    int x = threadIdx.x, y = threadIdx.y;
#pragma unroll
    for (int j = 0; j < 32; j += 8)
        t[y + j][x] = W[(size_t)(k0 + y + j) * N + n0 + x];
    __syncthreads();
#pragma unroll
    for (int j = 0; j < 32; j += 8) {
        float v = t[x][y + j];
        __nv_bfloat16 h = __float2bfloat16(v);
        __nv_bfloat16 l = __float2bfloat16(v - __bfloat162float(h));
        size_t off = (size_t)(n0 + y + j) * K + k0 + x;
        Th[off] = h;
        Tl[off] = l;
    }
}

// ---------------------------------------------------------------------------
// mma.sync bf16 3-pass GEMM: C[M,Ndim] = A[M,K] @ Bt[Ndim,K]^T
// CTA 128x128, BK=32, 8 warps (2x4), warp tile 64x32, cp.async double buffer.
// smem pitch = 40 halves (80B) -> conflict-free ldmatrix.
// ---------------------------------------------------------------------------
#define PITCH_H 40            // halves per row (32 data + 8 pad)
#define ARR_BYTES (128 * PITCH_H * 2)          // 10240
#define OFF_AH 0
#define OFF_AL (1 * ARR_BYTES)
#define OFF_BH (2 * ARR_BYTES)
#define OFF_BL (3 * ARR_BYTES)
#define STAGE_B (4 * ARR_BYTES)                // 40960
#define GEMM_SMEM (2 * STAGE_B)                // 81920

__global__ __launch_bounds__(256) void gemm_mma_bf16x3(
    const __nv_bfloat16* __restrict__ Ah_, const __nv_bfloat16* __restrict__ Al_,
    const __nv_bfloat16* __restrict__ Bh_, const __nv_bfloat16* __restrict__ Bl_,
    float* __restrict__ C, int Ndim, int Kdim)
{
    extern __shared__ __align__(16) char sm[];
    const uint32_t sbase = smem_u32(sm);
    const int tid  = threadIdx.x;
    const int lane = tid & 31;
    const int wid  = tid >> 5;
    const int wm   = wid >> 2;      // 0..1
    const int wn   = wid & 3;       // 0..3
    const int row0 = blockIdx.y * 128;
    const int col0 = blockIdx.x * 128;

    // ---- per-thread gmem sources + smem dests for cp.async (8 x 16B) ----
    const __nv_bfloat16* gsrc[8];
    uint32_t sdst[8];
#pragma unroll
    for (int j = 0; j < 2; j++) {
        int v = tid + 256 * j;          // 0..511
        int row = v >> 2, c16 = v & 3;
        size_t ga = (size_t)(row0 + row) * Kdim + c16 * 8;
        size_t gb = (size_t)(col0 + row) * Kdim + c16 * 8;
        uint32_t so = (uint32_t)row * (PITCH_H * 2) + c16 * 16;
        gsrc[j*4+0] = Ah_ + ga;  sdst[j*4+0] = OFF_AH + so;
        gsrc[j*4+1] = Al_ + ga;  sdst[j*4+1] = OFF_AL + so;
        gsrc[j*4+2] = Bh_ + gb;  sdst[j*4+2] = OFF_BH + so;
        gsrc[j*4+3] = Bl_ + gb;  sdst[j*4+3] = OFF_BL + so;
    }

    // ---- ldmatrix base offsets (bytes, within one array) ----
    // A frag (m16k16): rows wm*64 + mt*16 + (lane&15), col bytes (lane>>4)*16 + ks*32
    const uint32_t aoff = (uint32_t)(wm * 64 + (lane & 15)) * (PITCH_H * 2) + (lane >> 4) * 16;
    // B frag x4 covers 2 n-tiles: rows wn*32 + np*16 + (lane>>4)*8 + (lane&7)
    const uint32_t boff = (uint32_t)(wn * 32 + (lane >> 4) * 8 + (lane & 7)) * (PITCH_H * 2)
                          + ((lane >> 3) & 1) * 16;

    float acc[4][4][4];
#pragma unroll
    for (int mt = 0; mt < 4; mt++)
#pragma unroll
        for (int nt = 0; nt < 4; nt++)
#pragma unroll
            for (int r = 0; r < 4; r++) acc[mt][nt][r] = 0.0f;

    const int NC = Kdim / 32;

    // prologue: stage 0
#pragma unroll
    for (int t = 0; t < 8; t++) cp16(sbase + sdst[t], gsrc[t]);
    cp_commit();

    for (int i = 0; i < NC; i++) {
        if (i + 1 < NC) {
            const uint32_t nb = sbase + ((i + 1) & 1) * STAGE_B;
            const __nv_bfloat16* const koff = (const __nv_bfloat16*)0 + (size_t)(i + 1) * 32;
#pragma unroll
            for (int t = 0; t < 8; t++) cp16(nb + sdst[t], gsrc[t] + (size_t)(i + 1) * 32);
            cp_commit();
            asm volatile("cp.async.wait_group 1;" ::: "memory");
        } else {
            asm volatile("cp.async.wait_group 0;" ::: "memory");
        }
        __syncthreads();

        const uint32_t st = sbase + (i & 1) * STAGE_B;
#pragma unroll
        for (int ks = 0; ks < 2; ks++) {
            const uint32_t kb = ks * 32;
            uint32_t ah[4][4], al[4][4], bh[4][2], bl[4][2];
#pragma unroll
            for (int mt = 0; mt < 4; mt++) {
                ldsm4(ah[mt][0], ah[mt][1], ah[mt][2], ah[mt][3],
                      st + OFF_AH + aoff + mt * 16 * (PITCH_H * 2) + kb);
                ldsm4(al[mt][0], al[mt][1], al[mt][2], al[mt][3],
                      st + OFF_AL + aoff + mt * 16 * (PITCH_H * 2) + kb);
            }
#pragma unroll
            for (int np = 0; np < 2; np++) {
                ldsm4(bh[np*2][0], bh[np*2][1], bh[np*2+1][0], bh[np*2+1][1],
                      st + OFF_BH + boff + np * 16 * (PITCH_H * 2) + kb);
                ldsm4(bl[np*2][0], bl[np*2][1], bl[np*2+1][0], bl[np*2+1][1],
                      st + OFF_BL + boff + np * 16 * (PITCH_H * 2) + kb);
            }
#pragma unroll
            for (int mt = 0; mt < 4; mt++)
#pragma unroll
                for (int nt = 0; nt < 4; nt++) {
                    mma_bf16(acc[mt][nt], ah[mt], bh[nt]);
                    mma_bf16(acc[mt][nt], ah[mt], bl[nt]);
                    mma_bf16(acc[mt][nt], al[mt], bh[nt]);
                }
        }
        __syncthreads();   // protect buffer (i&1) before reload at iter i+1
    }

    // epilogue: c0,c1 contiguous -> float2 stores
#pragma unroll
    for (int mt = 0; mt < 4; mt++) {
        int r = row0 + wm * 64 + mt * 16 + (lane >> 2);
#pragma unroll
        for (int nt = 0; nt < 4; nt++) {
            int c = col0 + wn * 32 + nt * 8 + (lane & 3) * 2;
            *(float2*)&C[(size_t)r * Ndim + c]       = make_float2(acc[mt][nt][0], acc[mt][nt][1]);
            *(float2*)&C[(size_t)(r + 8) * Ndim + c] = make_float2(acc[mt][nt][2], acc[mt][nt][3]);
        }
    }
}

// ---------------------------------------------------------------------------
// RoPE (interleaved pairs)
// ---------------------------------------------------------------------------
__global__ void rope_kernel(float* __restrict__ q, const float* __restrict__ cs,
                            const float* __restrict__ sn, int nheads, int total)
{
    int idx = blockIdx.x * blockDim.x + threadIdx.x;
    if (idx >= total) return;
    int p    = idx & 63;
    int rest = idx >> 6;
    int bs   = rest / nheads;
    int s    = bs & (S_LEN - 1);
    float c  = cs[s * 64 + p];
    float sv = sn[s * 64 + p];
    size_t off = (size_t)rest * HDIM + 2 * p;
    float x0 = q[off], x1 = q[off + 1];
    q[off]     = x0 * c  - x1 * sv;
    q[off + 1] = x0 * sv + x1 * c;
}

// ---------------------------------------------------------------------------
// Causal flash attention, fp32 (unchanged, known-good)
// ---------------------------------------------------------------------------
#define BR 64
#define BC 64
#define LDQ 132
#define LDK 129
#define LDV 132
#define LDP 65
#define FLASH_SMEM ((BR * LDQ + BC * LDK + BC * LDV + BR * LDP) * 4)

__global__ __launch_bounds__(256) void flash_kernel(
    const float* __restrict__ Q, const float* __restrict__ Kg,
    const float* __restrict__ Vg, float* __restrict__ O)
{
    extern __shared__ float smf[];
    float* Qs = smf;
    float* Ks = Qs + BR * LDQ;
    float* Vs = Ks + BC * LDK;
    float* Ps = Vs + BC * LDV;

    const int tid = threadIdx.x;
    const int tx  = tid & 15;
    const int ty  = tid >> 4;
    const int qt  = blockIdx.x;
    const int h   = blockIdx.y;
    const int b   = blockIdx.z;
    const int g   = h >> 2;
    const int q0  = qt * BR;

    for (int idx = tid; idx < BR * HDIM; idx += 256) {
        int r = idx >> 7, d = idx & 127;
        Qs[r * LDQ + d] = Q[((size_t)(b * S_LEN + q0 + r) * NH + h) * HDIM + d];
    }

    float m_prev[4], l[4], acc[4][8];
#pragma unroll
    for (int i = 0; i < 4; i++) {
        m_prev[i] = -3.0e38f;
        l[i] = 0.0f;
#pragma unroll
        for (int c = 0; c < 8; c++) acc[i][c] = 0.0f;
    }

    const float scale = 0.08838834764831845f;

    for (int jt = 0; jt <= qt; jt++) {
        const int j0 = jt * BC;
        __syncthreads();

        for (int idx = tid; idx < BC * HDIM; idx += 256) {
            int r = idx >> 7, d = idx & 127;
            Ks[r * LDK + d] = Kg[((size_t)(b * S_LEN + j0 + r) * NKV + g) * HDIM + d];
        }
        for (int idx = tid; idx < BC * (HDIM / 4); idx += 256) {
            int r = idx >> 5, c4 = idx & 31;
            float4 vv = *(const float4*)&Vg[((size_t)(b * S_LEN + j0 + r) * NKV + g) * HDIM + c4 * 4];
            *(float4*)&Vs[r * LDV + c4 * 4] = vv;
        }
        __syncthreads();

        float sv[4][4];
#pragma unroll
        for (int i = 0; i < 4; i++)
#pragma unroll
            for (int j = 0; j < 4; j++) sv[i][j] = 0.0f;

#pragma unroll 4
        for (int d = 0; d < HDIM; d++) {
            float aq[4], bk[4];
#pragma unroll
            for (int i = 0; i < 4; i++) aq[i] = Qs[(ty * 4 + i) * LDQ + d];
#pragma unroll
            for (int j = 0; j < 4; j++) bk[j] = Ks[(tx * 4 + j) * LDK + d];
#pragma unroll
            for (int i = 0; i < 4; i++)
#pragma unroll
                for (int j = 0; j < 4; j++)
                    sv[i][j] = fmaf(aq[i], bk[j], sv[i][j]);
        }

        const bool diag = (jt == qt);
#pragma unroll
        for (int i = 0; i < 4; i++) {
            int qi = q0 + ty * 4 + i;
#pragma unroll
            for (int j = 0; j < 4; j++) {
                float s = sv[i][j] * scale;
                if (diag && (j0 + tx * 4 + j > qi)) s = -1.0e30f;
                sv[i][j] = s;
            }
        }

#pragma unroll
        for (int i = 0; i < 4; i++) {
            float mt = fmaxf(fmaxf(sv[i][0], sv[i][1]), fmaxf(sv[i][2], sv[i][3]));
#pragma unroll
            for (int off = 8; off > 0; off >>= 1)
                mt = fmaxf(mt, __shfl_xor_sync(0xffffffffu, mt, off));
            float mnew = fmaxf(m_prev[i], mt);
            float corr = __expf(m_prev[i] - mnew);
            float rl = 0.0f;
#pragma unroll
            for (int j = 0; j < 4; j++) {
                float p = __expf(sv[i][j] - mnew);
                Ps[(ty * 4 + i) * LDP + tx * 4 + j] = p;
                rl += p;
            }
#pragma unroll
            for (int off = 8; off > 0; off >>= 1)
                rl += __shfl_xor_sync(0xffffffffu, rl, off);
            l[i] = l[i] * corr + rl;
            m_prev[i] = mnew;
#pragma unroll
            for (int c = 0; c < 8; c++) acc[i][c] *= corr;
        }
        __syncthreads();

#pragma unroll 2
        for (int j = 0; j < BC; j++) {
            float4 v0 = *(const float4*)&Vs[j * LDV + tx * 4];
            float4 v1 = *(const float4*)&Vs[j * LDV + 64 + tx * 4];
#pragma unroll
            for (int i = 0; i < 4; i++) {
                float p = Ps[(ty * 4 + i) * LDP + j];
                acc[i][0] = fmaf(p, v0.x, acc[i][0]);
                acc[i][1] = fmaf(p, v0.y, acc[i][1]);
                acc[i][2] = fmaf(p, v0.z, acc[i][2]);
                acc[i][3] = fmaf(p, v0.w, acc[i][3]);
                acc[i][4] = fmaf(p, v1.x, acc[i][4]);
                acc[i][5] = fmaf(p, v1.y, acc[i][5]);
                acc[i][6] = fmaf(p, v1.z, acc[i][6]);
                acc[i][7] = fmaf(p, v1.w, acc[i][7]);
            }
        }
    }

#pragma unroll
    for (int i = 0; i < 4; i++) {
        float inv = 1.0f / l[i];
        size_t base = ((size_t)(b * S_LEN + q0 + ty * 4 + i) * NH + h) * HDIM;
#pragma unroll
        for (int cc = 0; cc < 4; cc++) {
            O[base + tx * 4 + cc]      = acc[i][cc]     * inv;
            O[base + 64 + tx * 4 + cc] = acc[i][cc + 4] * inv;
        }
    }
}

// ---------------------------------------------------------------------------
// Launch
// ---------------------------------------------------------------------------
extern "C" void kernel_launch(void* const* d_in, const int* in_sizes, int n_in,
                              void* d_out, int out_size)
{
    const float* x  = (const float*)d_in[0];
    const float* wq = (const float*)d_in[1];
    const float* wk = (const float*)d_in[2];
    const float* wv = (const float*)d_in[3];
    const float* wo = (const float*)d_in[4];
    const float* fc = (const float*)d_in[5];
    const float* fs = (const float*)d_in[6];
    float* out = (float*)d_out;

    float *q, *k, *v, *o;
    cudaGetSymbolAddress((void**)&q, g_q);
    cudaGetSymbolAddress((void**)&k, g_k);
    cudaGetSymbolAddress((void**)&v, g_v);
    cudaGetSymbolAddress((void**)&o, g_o);
    __nv_bfloat16 *xh, *xl, *wqth, *wqtl, *wkth, *wktl, *wvth, *wvtl, *woth, *wotl, *oh, *ol;
    cudaGetSymbolAddress((void**)&xh, g_xh);      cudaGetSymbolAddress((void**)&xl, g_xl);
    cudaGetSymbolAddress((void**)&wqth, g_wqt_h); cudaGetSymbolAddress((void**)&wqtl, g_wqt_l);
    cudaGetSymbolAddress((void**)&wkth, g_wkt_h); cudaGetSymbolAddress((void**)&wktl, g_wkt_l);
    cudaGetSymbolAddress((void**)&wvth, g_wvt_h); cudaGetSymbolAddress((void**)&wvtl, g_wvt_l);
    cudaGetSymbolAddress((void**)&woth, g_wot_h); cudaGetSymbolAddress((void**)&wotl, g_wot_l);
    cudaGetSymbolAddress((void**)&oh, g_oh);      cudaGetSymbolAddress((void**)&ol, g_ol);

    // split inputs / weights into bf16 hi/lo
    int n4 = (MROWS * DMODEL) / 4;
    split4_kernel<<<(n4 + 255) / 256, 256>>>(x, xh, xl, n4);
    split_transpose_kernel<<<dim3(DMODEL / 32, DMODEL / 32), dim3(32, 8)>>>(wq, wqth, wqtl, DMODEL, DMODEL);
    split_transpose_kernel<<<dim3((NKV * HDIM) / 32, DMODEL / 32), dim3(32, 8)>>>(wk, wkth, wktl, DMODEL, NKV * HDIM);
    split_transpose_kernel<<<dim3((NKV * HDIM) / 32, DMODEL / 32), dim3(32, 8)>>>(wv, wvth, wvtl, DMODEL, NKV * HDIM);
    split_transpose_kernel<<<dim3(DMODEL / 32, DMODEL / 32), dim3(32, 8)>>>(wo, woth, wotl, DMODEL, DMODEL);

    cudaFuncSetAttribute(gemm_mma_bf16x3, cudaFuncAttributeMaxDynamicSharedMemorySize, GEMM_SMEM);

    // QKV projections (tensor cores, mma.sync)
    gemm_mma_bf16x3<<<dim3((NH * HDIM) / 128,  MROWS / 128), 256, GEMM_SMEM>>>(xh, xl, wqth, wqtl, q, NH * HDIM,  DMODEL);
    gemm_mma_bf16x3<<<dim3((NKV * HDIM) / 128, MROWS / 128), 256, GEMM_SMEM>>>(xh, xl, wkth, wktl, k, NKV * HDIM, DMODEL);
    gemm_mma_bf16x3<<<dim3((NKV * HDIM) / 128, MROWS / 128), 256, GEMM_SMEM>>>(xh, xl, wvth, wvtl, v, NKV * HDIM, DMODEL);

    // RoPE
    int qtot = MROWS * NH  * 64;
    int ktot = MROWS * NKV * 64;
    rope_kernel<<<(qtot + 255) / 256, 256>>>(q, fc, fs, NH,  qtot);
    rope_kernel<<<(ktot + 255) / 256, 256>>>(k, fc, fs, NKV, ktot);

    // Attention (fp32 flash)
    cudaFuncSetAttribute(flash_kernel, cudaFuncAttributeMaxDynamicSharedMemorySize, FLASH_SMEM);
    flash_kernel<<<dim3(S_LEN / BR, NH, BATCH), 256, FLASH_SMEM>>>(q, k, v, o);

    // split attention output, then output projection
    split4_kernel<<<(n4 + 255) / 256, 256>>>(o, oh, ol, n4);
    gemm_mma_bf16x3<<<dim3(DMODEL / 128, MROWS / 128), 256, GEMM_SMEM>>>(oh, ol, woth, wotl, out, DMODEL, DMODEL);
}

// round 5
// speedup vs baseline: 2.8131x; 1.6083x over previous
#include <cuda_runtime.h>
#include <cuda_bf16.h>
#include <math.h>
#include <stdint.h>

#define S_LEN  2048
#define BATCH  2
#define DMODEL 4096
#define NH     32
#define NKV    8
#define HDIM   128
#define MROWS  (BATCH * S_LEN)   // 4096

// ---------------- scratch (__device__ globals; no allocs allowed) ----------
__device__ __align__(16) float g_q[(size_t)MROWS * NH * HDIM];
__device__ __align__(16) float g_k[(size_t)MROWS * NKV * HDIM];
__device__ __align__(16) float g_v[(size_t)MROWS * NKV * HDIM];

__device__ __align__(16) __nv_bfloat16 g_xh[(size_t)MROWS * DMODEL];   // reused as q_hi
__device__ __align__(16) __nv_bfloat16 g_xl[(size_t)MROWS * DMODEL];   // reused as q_lo
__device__ __align__(16) __nv_bfloat16 g_kh[(size_t)MROWS * NKV * HDIM];
__device__ __align__(16) __nv_bfloat16 g_kl[(size_t)MROWS * NKV * HDIM];
__device__ __align__(16) __nv_bfloat16 g_vh[(size_t)MROWS * NKV * HDIM];
__device__ __align__(16) __nv_bfloat16 g_vl[(size_t)MROWS * NKV * HDIM];
__device__ __align__(16) __nv_bfloat16 g_wqt_h[(size_t)DMODEL * DMODEL];
__device__ __align__(16) __nv_bfloat16 g_wqt_l[(size_t)DMODEL * DMODEL];
__device__ __align__(16) __nv_bfloat16 g_wkt_h[(size_t)(NKV*HDIM) * DMODEL];
__device__ __align__(16) __nv_bfloat16 g_wkt_l[(size_t)(NKV*HDIM) * DMODEL];
__device__ __align__(16) __nv_bfloat16 g_wvt_h[(size_t)(NKV*HDIM) * DMODEL];
__device__ __align__(16) __nv_bfloat16 g_wvt_l[(size_t)(NKV*HDIM) * DMODEL];
__device__ __align__(16) __nv_bfloat16 g_wot_h[(size_t)DMODEL * DMODEL];
__device__ __align__(16) __nv_bfloat16 g_wot_l[(size_t)DMODEL * DMODEL];
__device__ __align__(16) __nv_bfloat16 g_oh[(size_t)MROWS * DMODEL];
__device__ __align__(16) __nv_bfloat16 g_ol[(size_t)MROWS * DMODEL];

// ---------------- helpers ---------------------------------------------------
__device__ __forceinline__ uint32_t smem_u32(const void* p) {
    return (uint32_t)__cvta_generic_to_shared(p);
}
__device__ __forceinline__ void cp16(uint32_t dst, const void* src) {
    asm volatile("cp.async.ca.shared.global [%0], [%1], 16;" :: "r"(dst), "l"(src) : "memory");
}
__device__ __forceinline__ void cp_commit() {
    asm volatile("cp.async.commit_group;" ::: "memory");
}
__device__ __forceinline__ void ldsm4(uint32_t& r0, uint32_t& r1, uint32_t& r2, uint32_t& r3,
                                      uint32_t addr) {
    asm volatile("ldmatrix.sync.aligned.m8n8.x4.shared.b16 {%0,%1,%2,%3}, [%4];"
                 : "=r"(r0), "=r"(r1), "=r"(r2), "=r"(r3) : "r"(addr));
}
__device__ __forceinline__ void ldsm4t(uint32_t& r0, uint32_t& r1, uint32_t& r2, uint32_t& r3,
                                       uint32_t addr) {
    asm volatile("ldmatrix.sync.aligned.m8n8.x4.trans.shared.b16 {%0,%1,%2,%3}, [%4];"
                 : "=r"(r0), "=r"(r1), "=r"(r2), "=r"(r3) : "r"(addr));
}
__device__ __forceinline__ void mma_bf16(float* d, const uint32_t* a, const uint32_t* b) {
    asm volatile("mma.sync.aligned.m16n8k16.row.col.f32.bf16.bf16.f32 "
                 "{%0,%1,%2,%3}, {%4,%5,%6,%7}, {%8,%9}, {%0,%1,%2,%3};"
                 : "+f"(d[0]), "+f"(d[1]), "+f"(d[2]), "+f"(d[3])
                 : "r"(a[0]), "r"(a[1]), "r"(a[2]), "r"(a[3]), "r"(b[0]), "r"(b[1]));
}
__device__ __forceinline__ uint32_t packbf(float lo, float hi) {
    uint32_t r;
    asm("cvt.rn.bf16x2.f32 %0, %1, %2;" : "=r"(r) : "f"(hi), "f"(lo));
    return r;
}

// ---------------------------------------------------------------------------
// fp32 -> (hi, lo) bf16 split, elementwise
// ---------------------------------------------------------------------------
__global__ void split4_kernel(const float* __restrict__ in,
                              __nv_bfloat16* __restrict__ h,
                              __nv_bfloat16* __restrict__ l, int n4)
{
    int i = blockIdx.x * blockDim.x + threadIdx.x;
    if (i >= n4) return;
    float4 x = ((const float4*)in)[i];
    __nv_bfloat16 h0 = __float2bfloat16(x.x), h1 = __float2bfloat16(x.y);
    __nv_bfloat16 h2 = __float2bfloat16(x.z), h3 = __float2bfloat16(x.w);
    __nv_bfloat16 l0 = __float2bfloat16(x.x - __bfloat162float(h0));
    __nv_bfloat16 l1 = __float2bfloat16(x.y - __bfloat162float(h1));
    __nv_bfloat16 l2 = __float2bfloat16(x.z - __bfloat162float(h2));
    __nv_bfloat16 l3 = __float2bfloat16(x.w - __bfloat162float(h3));
    ((__nv_bfloat162*)h)[2*i]   = __nv_bfloat162(h0, h1);
    ((__nv_bfloat162*)h)[2*i+1] = __nv_bfloat162(h2, h3);
    ((__nv_bfloat162*)l)[2*i]   = __nv_bfloat162(l0, l1);
    ((__nv_bfloat162*)l)[2*i+1] = __nv_bfloat162(l2, l3);
}

// ---------------------------------------------------------------------------
// RoPE + split: rotate fp32 pairs, emit bf16 hi/lo
// ---------------------------------------------------------------------------
__global__ void rope_split_kernel(const float* __restrict__ src,
                                  const float* __restrict__ cs, const float* __restrict__ sn,
                                  __nv_bfloat16* __restrict__ dh, __nv_bfloat16* __restrict__ dl,
                                  int nheads, int total)
{
    int idx = blockIdx.x * blockDim.x + threadIdx.x;
    if (idx >= total) return;
    int p    = idx & 63;
    int rest = idx >> 6;
    int s    = (rest / nheads) & (S_LEN - 1);
    float c  = cs[s * 64 + p];
    float sv = sn[s * 64 + p];
    size_t off = (size_t)rest * HDIM + 2 * p;
    float2 x = *(const float2*)&src[off];
    float o0 = x.x * c  - x.y * sv;
    float o1 = x.x * sv + x.y * c;
    __nv_bfloat16 h0 = __float2bfloat16(o0), h1 = __float2bfloat16(o1);
    *(__nv_bfloat162*)&dh[off] = __nv_bfloat162(h0, h1);
    *(__nv_bfloat162*)&dl[off] = __nv_bfloat162(
        __float2bfloat16(o0 - __bfloat162float(h0)),
        __float2bfloat16(o1 - __bfloat162float(h1)));
}

// ---------------------------------------------------------------------------
// W[K,N] fp32 -> WT[N,K] (hi, lo) bf16, tiled transpose
// ---------------------------------------------------------------------------
__global__ void split_transpose_kernel(const float* __restrict__ W,
                                       __nv_bfloat16* __restrict__ Th,
                                       __nv_bfloat16* __restrict__ Tl,
                                       int K, int N)
{
    __shared__ float t[32][33];
    int k0 = blockIdx.y * 32, n0 = blockIdx.x * 32;
    int x = threadIdx.x, y = threadIdx.y;
#pragma unroll
    for (int j = 0; j < 32; j += 8)
        t[y + j][x] = W[(size_t)(k0 + y + j) * N + n0 + x];
    __syncthreads();
#pragma unroll
    for (int j = 0; j < 32; j += 8) {
        float v = t[x][y + j];
        __nv_bfloat16 h = __float2bfloat16(v);
        __nv_bfloat16 l = __float2bfloat16(v - __bfloat162float(h));
        size_t off = (size_t)(n0 + y + j) * K + k0 + x;
        Th[off] = h;
        Tl[off] = l;
    }
}

// ---------------------------------------------------------------------------
// mma.sync bf16 3-pass GEMM (unchanged from R4, known-good)
// ---------------------------------------------------------------------------
#define PITCH_H 40
#define ARR_BYTES (128 * PITCH_H * 2)
#define OFF_AH 0
#define OFF_AL (1 * ARR_BYTES)
#define OFF_BH (2 * ARR_BYTES)
#define OFF_BL (3 * ARR_BYTES)
#define STAGE_B (4 * ARR_BYTES)
#define GEMM_SMEM (2 * STAGE_B)

__global__ __launch_bounds__(256) void gemm_mma_bf16x3(
    const __nv_bfloat16* __restrict__ Ah_, const __nv_bfloat16* __restrict__ Al_,
    const __nv_bfloat16* __restrict__ Bh_, const __nv_bfloat16* __restrict__ Bl_,
    float* __restrict__ C, int Ndim, int Kdim)
{
    extern __shared__ __align__(16) char sm[];
    const uint32_t sbase = smem_u32(sm);
    const int tid  = threadIdx.x;
    const int lane = tid & 31;
    const int wid  = tid >> 5;
    const int wm   = wid >> 2;
    const int wn   = wid & 3;
    const int row0 = blockIdx.y * 128;
    const int col0 = blockIdx.x * 128;

    const __nv_bfloat16* gsrc[8];
    uint32_t sdst[8];
#pragma unroll
    for (int j = 0; j < 2; j++) {
        int v = tid + 256 * j;
        int row = v >> 2, c16 = v & 3;
        size_t ga = (size_t)(row0 + row) * Kdim + c16 * 8;
        size_t gb = (size_t)(col0 + row) * Kdim + c16 * 8;
        uint32_t so = (uint32_t)row * (PITCH_H * 2) + c16 * 16;
        gsrc[j*4+0] = Ah_ + ga;  sdst[j*4+0] = OFF_AH + so;
        gsrc[j*4+1] = Al_ + ga;  sdst[j*4+1] = OFF_AL + so;
        gsrc[j*4+2] = Bh_ + gb;  sdst[j*4+2] = OFF_BH + so;
        gsrc[j*4+3] = Bl_ + gb;  sdst[j*4+3] = OFF_BL + so;
    }

    const uint32_t aoff = (uint32_t)(wm * 64 + (lane & 15)) * (PITCH_H * 2) + (lane >> 4) * 16;
    const uint32_t boff = (uint32_t)(wn * 32 + (lane >> 4) * 8 + (lane & 7)) * (PITCH_H * 2)
                          + ((lane >> 3) & 1) * 16;

    float acc[4][4][4];
#pragma unroll
    for (int mt = 0; mt < 4; mt++)
#pragma unroll
        for (int nt = 0; nt < 4; nt++)
#pragma unroll
            for (int r = 0; r < 4; r++) acc[mt][nt][r] = 0.0f;

    const int NC = Kdim / 32;

#pragma unroll
    for (int t = 0; t < 8; t++) cp16(sbase + sdst[t], gsrc[t]);
    cp_commit();

    for (int i = 0; i < NC; i++) {
        if (i + 1 < NC) {
            const uint32_t nb = sbase + ((i + 1) & 1) * STAGE_B;
#pragma unroll
            for (int t = 0; t < 8; t++) cp16(nb + sdst[t], gsrc[t] + (size_t)(i + 1) * 32);
            cp_commit();
            asm volatile("cp.async.wait_group 1;" ::: "memory");
        } else {
            asm volatile("cp.async.wait_group 0;" ::: "memory");
        }
        __syncthreads();

        const uint32_t st = sbase + (i & 1) * STAGE_B;
#pragma unroll
        for (int ks = 0; ks < 2; ks++) {
            const uint32_t kb = ks * 32;
            uint32_t ah[4][4], al[4][4], bh[4][2], bl[4][2];
#pragma unroll
            for (int mt = 0; mt < 4; mt++) {
                ldsm4(ah[mt][0], ah[mt][1], ah[mt][2], ah[mt][3],
                      st + OFF_AH + aoff + mt * 16 * (PITCH_H * 2) + kb);
                ldsm4(al[mt][0], al[mt][1], al[mt][2], al[mt][3],
                      st + OFF_AL + aoff + mt * 16 * (PITCH_H * 2) + kb);
            }
#pragma unroll
            for (int np = 0; np < 2; np++) {
                ldsm4(bh[np*2][0], bh[np*2][1], bh[np*2+1][0], bh[np*2+1][1],
                      st + OFF_BH + boff + np * 16 * (PITCH_H * 2) + kb);
                ldsm4(bl[np*2][0], bl[np*2][1], bl[np*2+1][0], bl[np*2+1][1],
                      st + OFF_BL + boff + np * 16 * (PITCH_H * 2) + kb);
            }
#pragma unroll
            for (int mt = 0; mt < 4; mt++)
#pragma unroll
                for (int nt = 0; nt < 4; nt++) {
                    mma_bf16(acc[mt][nt], ah[mt], bh[nt]);
                    mma_bf16(acc[mt][nt], ah[mt], bl[nt]);
                    mma_bf16(acc[mt][nt], al[mt], bh[nt]);
                }
        }
        __syncthreads();
    }

#pragma unroll
    for (int mt = 0; mt < 4; mt++) {
        int r = row0 + wm * 64 + mt * 16 + (lane >> 2);
#pragma unroll
        for (int nt = 0; nt < 4; nt++) {
            int c = col0 + wn * 32 + nt * 8 + (lane & 3) * 2;
            *(float2*)&C[(size_t)r * Ndim + c]       = make_float2(acc[mt][nt][0], acc[mt][nt][1]);
            *(float2*)&C[(size_t)(r + 8) * Ndim + c] = make_float2(acc[mt][nt][2], acc[mt][nt][3]);
        }
    }
}

// ---------------------------------------------------------------------------
// Tensor-core causal flash attention (bf16 3-pass split, FA2 layout).
// Grid: (S/64, NH, B); 128 threads; warp w owns rows [w*16, w*16+16).
// Writes bf16 hi/lo output directly (for the final GEMM).
// ---------------------------------------------------------------------------
#define FBR 64
#define FBC 64
#define FP  136                  // smem pitch in halves (272 B)
#define FAB (FBR * FP)           // halves per array
#define FLASH2_SMEM (6 * FAB * 2)

__global__ __launch_bounds__(128) void flash_tc(
    const __nv_bfloat16* __restrict__ Qh_, const __nv_bfloat16* __restrict__ Ql_,
    const __nv_bfloat16* __restrict__ Kh_, const __nv_bfloat16* __restrict__ Kl_,
    const __nv_bfloat16* __restrict__ Vh_, const __nv_bfloat16* __restrict__ Vl_,
    __nv_bfloat16* __restrict__ Oh_, __nv_bfloat16* __restrict__ Ol_)
{
    extern __shared__ __align__(16) __nv_bfloat16 smh[];
    const int tid  = threadIdx.x;
    const int lane = tid & 31;
    const int w    = tid >> 5;
    const int qt   = gridDim.x - 1 - blockIdx.x;   // long CTAs first
    const int h    = blockIdx.y;
    const int b    = blockIdx.z;
    const int g    = h >> 2;                       // NREP = 4
    const int q0   = qt * FBR;

    const uint32_t sb = smem_u32(smh);
    // byte offsets of arrays within smem
    const uint32_t oQh = 0, oQl = FAB*2, oKh = 4*FAB, oKl = 6*FAB, oVh = 8*FAB, oVl = 10*FAB;

    // load Q tile (rows = tokens for head h)
    for (int i = tid; i < FBR * 16; i += 128) {
        int r = i >> 4, c = i & 15;
        size_t gq = ((size_t)((b*S_LEN + q0 + r) * NH) + h) * HDIM + c * 8;
        *(uint4*)&smh[r*FP + c*8]        = *(const uint4*)&Qh_[gq];
        *(uint4*)&smh[FAB + r*FP + c*8]  = *(const uint4*)&Ql_[gq];
    }

    // ldmatrix byte offsets
    const uint32_t aoff = ((uint32_t)(w*16 + (lane & 15)) * FP) * 2 + (lane >> 4) * 16;
    const uint32_t boff = ((uint32_t)((lane >> 4) * 8 + (lane & 7)) * FP) * 2 + ((lane >> 3) & 1) * 16;
    const uint32_t voff = ((uint32_t)(((lane >> 3) & 1) * 8 + (lane & 7)) * FP) * 2 + (lane >> 4) * 16;

    float oacc[16][4];
#pragma unroll
    for (int t = 0; t < 16; t++)
#pragma unroll
        for (int r = 0; r < 4; r++) oacc[t][r] = 0.0f;
    float m0 = -3.0e38f, m1 = -3.0e38f, l0 = 0.0f, l1 = 0.0f;

    const float scale = 0.08838834764831845f;

    for (int jt = 0; jt <= qt; jt++) {
        const int j0 = jt * FBC;
        __syncthreads();
        for (int i = tid; i < FBC * 16; i += 128) {
            int r = i >> 4, c = i & 15;
            size_t gk = ((size_t)((b*S_LEN + j0 + r) * NKV) + g) * HDIM + c * 8;
            *(uint4*)&smh[2*FAB + r*FP + c*8] = *(const uint4*)&Kh_[gk];
            *(uint4*)&smh[3*FAB + r*FP + c*8] = *(const uint4*)&Kl_[gk];
            *(uint4*)&smh[4*FAB + r*FP + c*8] = *(const uint4*)&Vh_[gk];
            *(uint4*)&smh[5*FAB + r*FP + c*8] = *(const uint4*)&Vl_[gk];
        }
        __syncthreads();

        // ---- S = Q K^T (3-pass split) ----
        float sv[8][4];
#pragma unroll
        for (int t = 0; t < 8; t++)
#pragma unroll
            for (int r = 0; r < 4; r++) sv[t][r] = 0.0f;

#pragma unroll
        for (int ks = 0; ks < 8; ks++) {
            uint32_t ah[4], al[4], bh[8][2], bl[8][2];
            ldsm4(ah[0], ah[1], ah[2], ah[3], sb + oQh + aoff + ks*32);
            ldsm4(al[0], al[1], al[2], al[3], sb + oQl + aoff + ks*32);
#pragma unroll
            for (int nn = 0; nn < 4; nn++) {
                uint32_t adr = sb + oKh + boff + nn * (16*FP*2) + ks*32;
                ldsm4(bh[2*nn][0], bh[2*nn][1], bh[2*nn+1][0], bh[2*nn+1][1], adr);
                ldsm4(bl[2*nn][0], bl[2*nn][1], bl[2*nn+1][0], bl[2*nn+1][1], adr + 2*FAB);
            }
#pragma unroll
            for (int t = 0; t < 8; t++) {
                mma_bf16(sv[t], ah, bh[t]);
                mma_bf16(sv[t], ah, bl[t]);
                mma_bf16(sv[t], al, bh[t]);
            }
        }

        // ---- scale + causal mask ----
#pragma unroll
        for (int t = 0; t < 8; t++) {
            sv[t][0] *= scale; sv[t][1] *= scale;
            sv[t][2] *= scale; sv[t][3] *= scale;
        }
        if (jt == qt) {
            int row = q0 + w*16 + (lane >> 2);
            int cb  = j0 + (lane & 3) * 2;
#pragma unroll
            for (int t = 0; t < 8; t++) {
                int c0 = cb + t*8;
                if (c0     > row    ) sv[t][0] = -1.0e30f;
                if (c0 + 1 > row    ) sv[t][1] = -1.0e30f;
                if (c0     > row + 8) sv[t][2] = -1.0e30f;
                if (c0 + 1 > row + 8) sv[t][3] = -1.0e30f;
            }
        }

        // ---- online softmax (rows g and g+8) ----
        float mx0 = -1.0e30f, mx1 = -1.0e30f;
#pragma unroll
        for (int t = 0; t < 8; t++) {
            mx0 = fmaxf(mx0, fmaxf(sv[t][0], sv[t][1]));
            mx1 = fmaxf(mx1, fmaxf(sv[t][2], sv[t][3]));
        }
        mx0 = fmaxf(mx0, __shfl_xor_sync(0xffffffffu, mx0, 1));
        mx0 = fmaxf(mx0, __shfl_xor_sync(0xffffffffu, mx0, 2));
        mx1 = fmaxf(mx1, __shfl_xor_sync(0xffffffffu, mx1, 1));
        mx1 = fmaxf(mx1, __shfl_xor_sync(0xffffffffu, mx1, 2));
        float mnew0 = fmaxf(m0, mx0), mnew1 = fmaxf(m1, mx1);
        float corr0 = __expf(m0 - mnew0), corr1 = __expf(m1 - mnew1);

        float rl0 = 0.0f, rl1 = 0.0f;
        uint32_t paH[4][4], paL[4][4];
#pragma unroll
        for (int u = 0; u < 4; u++) {
            float p00 = __expf(sv[2*u][0]   - mnew0), p01 = __expf(sv[2*u][1]   - mnew0);
            float p02 = __expf(sv[2*u][2]   - mnew1), p03 = __expf(sv[2*u][3]   - mnew1);
            float p10 = __expf(sv[2*u+1][0] - mnew0), p11 = __expf(sv[2*u+1][1] - mnew0);
            float p12 = __expf(sv[2*u+1][2] - mnew1), p13 = __expf(sv[2*u+1][3] - mnew1);
            rl0 += p00 + p01 + p10 + p11;
            rl1 += p02 + p03 + p12 + p13;
            paH[u][0] = packbf(p00, p01);
            paH[u][1] = packbf(p02, p03);
            paH[u][2] = packbf(p10, p11);
            paH[u][3] = packbf(p12, p13);
            float q00 = p00 - __bfloat162float(__float2bfloat16(p00));
            float q01 = p01 - __bfloat162float(__float2bfloat16(p01));
            float q02 = p02 - __bfloat162float(__float2bfloat16(p02));
            float q03 = p03 - __bfloat162float(__float2bfloat16(p03));
            float q10 = p10 - __bfloat162float(__float2bfloat16(p10));
            float q11 = p11 - __bfloat162float(__float2bfloat16(p11));
            float q12 = p12 - __bfloat162float(__float2bfloat16(p12));
            float q13 = p13 - __bfloat162float(__float2bfloat16(p13));
            paL[u][0] = packbf(q00, q01);
            paL[u][1] = packbf(q02, q03);
            paL[u][2] = packbf(q10, q11);
            paL[u][3] = packbf(q12, q13);
        }
        rl0 += __shfl_xor_sync(0xffffffffu, rl0, 1);
        rl0 += __shfl_xor_sync(0xffffffffu, rl0, 2);
        rl1 += __shfl_xor_sync(0xffffffffu, rl1, 1);
        rl1 += __shfl_xor_sync(0xffffffffu, rl1, 2);
        l0 = l0 * corr0 + rl0;
        l1 = l1 * corr1 + rl1;
        m0 = mnew0; m1 = mnew1;
#pragma unroll
        for (int t = 0; t < 16; t++) {
            oacc[t][0] *= corr0; oacc[t][1] *= corr0;
            oacc[t][2] *= corr1; oacc[t][3] *= corr1;
        }

        // ---- O += P V (3-pass split, V^T via ldmatrix.trans) ----
#pragma unroll
        for (int u = 0; u < 4; u++) {
#pragma unroll
            for (int dh2 = 0; dh2 < 2; dh2++) {
                uint32_t bvh[8][2], bvl[8][2];
#pragma unroll
                for (int dd = 0; dd < 4; dd++) {
                    uint32_t adr = sb + oVh + voff + u * (16*FP*2) + (dh2*64 + dd*16) * 2;
                    ldsm4t(bvh[2*dd][0], bvh[2*dd][1], bvh[2*dd+1][0], bvh[2*dd+1][1], adr);
                    ldsm4t(bvl[2*dd][0], bvl[2*dd][1], bvl[2*dd+1][0], bvl[2*dd+1][1], adr + 2*FAB);
                }
#pragma unroll
                for (int t = 0; t < 8; t++) {
                    mma_bf16(oacc[dh2*8+t], paH[u], bvh[t]);
                    mma_bf16(oacc[dh2*8+t], paH[u], bvl[t]);
                    mma_bf16(oacc[dh2*8+t], paL[u], bvh[t]);
                }
            }
        }
    }

    // ---- epilogue: divide by l, split to bf16 hi/lo, store ----
    float inv0 = 1.0f / l0, inv1 = 1.0f / l1;
    int rowa = b*S_LEN + q0 + w*16 + (lane >> 2);
    size_t base0 = ((size_t)rowa * NH + h) * HDIM;
    size_t base1 = base0 + (size_t)8 * NH * HDIM;
#pragma unroll
    for (int t = 0; t < 16; t++) {
        int c = t*8 + (lane & 3) * 2;
        float v0 = oacc[t][0] * inv0, v1 = oacc[t][1] * inv0;
        float v2 = oacc[t][2] * inv1, v3 = oacc[t][3] * inv1;
        __nv_bfloat16 h0 = __float2bfloat16(v0), h1 = __float2bfloat16(v1);
        __nv_bfloat16 h2 = __float2bfloat16(v2), h3 = __float2bfloat16(v3);
        *(__nv_bfloat162*)&Oh_[base0 + c] = __nv_bfloat162(h0, h1);
        *(__nv_bfloat162*)&Oh_[base1 + c] = __nv_bfloat162(h2, h3);
        *(__nv_bfloat162*)&Ol_[base0 + c] = __nv_bfloat162(
            __float2bfloat16(v0 - __bfloat162float(h0)),
            __float2bfloat16(v1 - __bfloat162float(h1)));
        *(__nv_bfloat162*)&Ol_[base1 + c] = __nv_bfloat162(
            __float2bfloat16(v2 - __bfloat162float(h2)),
            __float2bfloat16(v3 - __bfloat162float(h3)));
    }
}

// ---------------------------------------------------------------------------
// Launch
// ---------------------------------------------------------------------------
extern "C" void kernel_launch(void* const* d_in, const int* in_sizes, int n_in,
                              void* d_out, int out_size)
{
    const float* x  = (const float*)d_in[0];
    const float* wq = (const float*)d_in[1];
    const float* wk = (const float*)d_in[2];
    const float* wv = (const float*)d_in[3];
    const float* wo = (const float*)d_in[4];
    const float* fc = (const float*)d_in[5];
    const float* fs = (const float*)d_in[6];
    float* out = (float*)d_out;

    float *q, *k, *v;
    cudaGetSymbolAddress((void**)&q, g_q);
    cudaGetSymbolAddress((void**)&k, g_k);
    cudaGetSymbolAddress((void**)&v, g_v);
    __nv_bfloat16 *xh, *xl, *kh, *kl, *vh, *vl;
    __nv_bfloat16 *wqth, *wqtl, *wkth, *wktl, *wvth, *wvtl, *woth, *wotl, *oh, *ol;
    cudaGetSymbolAddress((void**)&xh, g_xh);      cudaGetSymbolAddress((void**)&xl, g_xl);
    cudaGetSymbolAddress((void**)&kh, g_kh);      cudaGetSymbolAddress((void**)&kl, g_kl);
    cudaGetSymbolAddress((void**)&vh, g_vh);      cudaGetSymbolAddress((void**)&vl, g_vl);
    cudaGetSymbolAddress((void**)&wqth, g_wqt_h); cudaGetSymbolAddress((void**)&wqtl, g_wqt_l);
    cudaGetSymbolAddress((void**)&wkth, g_wkt_h); cudaGetSymbolAddress((void**)&wktl, g_wkt_l);
    cudaGetSymbolAddress((void**)&wvth, g_wvt_h); cudaGetSymbolAddress((void**)&wvtl, g_wvt_l);
    cudaGetSymbolAddress((void**)&woth, g_wot_h); cudaGetSymbolAddress((void**)&wotl, g_wot_l);
    cudaGetSymbolAddress((void**)&oh, g_oh);      cudaGetSymbolAddress((void**)&ol, g_ol);

    // split inputs / weights into bf16 hi/lo
    int n4 = (MROWS * DMODEL) / 4;
    split4_kernel<<<(n4 + 255) / 256, 256>>>(x, xh, xl, n4);
    split_transpose_kernel<<<dim3(DMODEL / 32, DMODEL / 32), dim3(32, 8)>>>(wq, wqth, wqtl, DMODEL, DMODEL);
    split_transpose_kernel<<<dim3((NKV * HDIM) / 32, DMODEL / 32), dim3(32, 8)>>>(wk, wkth, wktl, DMODEL, NKV * HDIM);
    split_transpose_kernel<<<dim3((NKV * HDIM) / 32, DMODEL / 32), dim3(32, 8)>>>(wv, wvth, wvtl, DMODEL, NKV * HDIM);
    split_transpose_kernel<<<dim3(DMODEL / 32, DMODEL / 32), dim3(32, 8)>>>(wo, woth, wotl, DMODEL, DMODEL);

    cudaFuncSetAttribute(gemm_mma_bf16x3, cudaFuncAttributeMaxDynamicSharedMemorySize, GEMM_SMEM);

    // QKV projections
    gemm_mma_bf16x3<<<dim3((NH * HDIM) / 128,  MROWS / 128), 256, GEMM_SMEM>>>(xh, xl, wqth, wqtl, q, NH * HDIM,  DMODEL);
    gemm_mma_bf16x3<<<dim3((NKV * HDIM) / 128, MROWS / 128), 256, GEMM_SMEM>>>(xh, xl, wkth, wktl, k, NKV * HDIM, DMODEL);
    gemm_mma_bf16x3<<<dim3((NKV * HDIM) / 128, MROWS / 128), 256, GEMM_SMEM>>>(xh, xl, wvth, wvtl, v, NKV * HDIM, DMODEL);

    // RoPE + bf16 split (q reuses xh/xl — safe, GEMMs above already consumed them)
    int qtot = MROWS * NH  * 64;
    int ktot = MROWS * NKV * 64;
    rope_split_kernel<<<(qtot + 255) / 256, 256>>>(q, fc, fs, xh, xl, NH,  qtot);
    rope_split_kernel<<<(ktot + 255) / 256, 256>>>(k, fc, fs, kh, kl, NKV, ktot);
    int v4 = (MROWS * NKV * HDIM) / 4;
    split4_kernel<<<(v4 + 255) / 256, 256>>>(v, vh, vl, v4);

    // Tensor-core flash attention -> bf16 hi/lo output
    cudaFuncSetAttribute(flash_tc, cudaFuncAttributeMaxDynamicSharedMemorySize, FLASH2_SMEM);
    flash_tc<<<dim3(S_LEN / FBR, NH, BATCH), 128, FLASH2_SMEM>>>(xh, xl, kh, kl, vh, vl, oh, ol);

    // Output projection
    gemm_mma_bf16x3<<<dim3(DMODEL / 128, MROWS / 128), 256, GEMM_SMEM>>>(oh, ol, woth, wotl, out, DMODEL, DMODEL);
}